// round 1
// baseline (speedup 1.0000x reference)
#include <cuda_runtime.h>
#include <cuda_bf16.h>
#include <math.h>

// Problem constants
#define Bv 16
#define Nv 1024
#define Fv 256
#define Gv 256
#define ECAT 4
#define NEDGES 16384
#define EMB 256
#define H1 512
#define H2 512
#define Mv (Bv * Nv)          // 16384 rows
#define DIN (Gv * ECAT)       // 1024
#define BN_EPS 1e-5f

// Scratch (static device globals; allocation-free)
__device__ float d_XW[(size_t)ECAT * Mv * Gv];   // [e][m][g]  64MB
__device__ float d_H [(size_t)Mv * DIN];         // [m][e*G+g] 64MB
__device__ float d_h0[(size_t)Mv * H1];          // 32MB
__device__ float d_h1[(size_t)Mv * H2];          // 32MB
__device__ float d_stats[4 * 512];               // sum0,sumsq0,sum1,sumsq1

// ---------------------------------------------------------------------------
// zero kernel (grid-stride float4)
// ---------------------------------------------------------------------------
__global__ void zero_kernel(float* __restrict__ p, size_t n4) {
    size_t i = (size_t)blockIdx.x * blockDim.x + threadIdx.x;
    size_t stride = (size_t)gridDim.x * blockDim.x;
    float4 z = make_float4(0.f, 0.f, 0.f, 0.f);
    for (; i < n4; i += stride) reinterpret_cast<float4*>(p)[i] = z;
}

// ---------------------------------------------------------------------------
// Generic tiled GEMM:  C[m][n] = sum_k A[m][k] * B(n,k) + bias[n]
//   B_T = true : Bw is [Nn][K] row-major (weight @ W.T case)
//   B_T = false: Bw is [K][Nn] row-major (X @ Ws case)
//   RELU_A: apply relu to A elements as they are loaded
// BM=128, BN=64, BK=16, 256 threads, 8x4 per-thread tile.
// M % 128 == 0, Nn % 64 == 0, K % 16 == 0 guaranteed by problem sizes.
// ---------------------------------------------------------------------------
template<bool B_T, bool RELU_A>
__global__ __launch_bounds__(256)
void gemm_bias(const float* __restrict__ A, const float* __restrict__ Bw,
               const float* __restrict__ bias, float* __restrict__ C,
               int M, int Nn, int K,
               size_t aStrideZ, size_t bStrideZ, size_t cStrideZ) {
    A  += (size_t)blockIdx.z * aStrideZ;
    Bw += (size_t)blockIdx.z * bStrideZ;
    C  += (size_t)blockIdx.z * cStrideZ;

    __shared__ float As[16][128];
    __shared__ float Bs[16][64];

    const int m0 = blockIdx.y * 128;
    const int n0 = blockIdx.x * 64;
    const int tid = threadIdx.x;
    const int tx = tid & 15;          // 16 threads across n (4 cols each)
    const int ty = tid >> 4;          // 16 threads across m (8 rows each)

    float acc[8][4];
#pragma unroll
    for (int i = 0; i < 8; i++)
#pragma unroll
        for (int j = 0; j < 4; j++) acc[i][j] = 0.f;

    for (int k0 = 0; k0 < K; k0 += 16) {
        // --- load A tile: 128x16 = 512 float4, 2 per thread ---
#pragma unroll
        for (int it = 0; it < 2; it++) {
            int idx = tid + it * 256;       // float4 slot
            int r = idx >> 2;               // row (4 float4 per row)
            int c = (idx & 3) << 2;         // k-col
            float4 v = *reinterpret_cast<const float4*>(&A[(size_t)(m0 + r) * K + k0 + c]);
            if (RELU_A) {
                v.x = fmaxf(v.x, 0.f); v.y = fmaxf(v.y, 0.f);
                v.z = fmaxf(v.z, 0.f); v.w = fmaxf(v.w, 0.f);
            }
            As[c + 0][r] = v.x; As[c + 1][r] = v.y;
            As[c + 2][r] = v.z; As[c + 3][r] = v.w;
        }
        // --- load B tile: 64x16 (B_T) or 16x64 (NT) = 256 float4, 1 per thread ---
        if (B_T) {
            int r = tid >> 2;               // n-row within tile (0..63)
            int c = (tid & 3) << 2;         // k-col
            float4 v = *reinterpret_cast<const float4*>(&Bw[(size_t)(n0 + r) * K + k0 + c]);
            Bs[c + 0][r] = v.x; Bs[c + 1][r] = v.y;
            Bs[c + 2][r] = v.z; Bs[c + 3][r] = v.w;
        } else {
            int r = tid >> 4;               // k-row (0..15)
            int c = (tid & 15) << 2;        // n-col
            float4 v = *reinterpret_cast<const float4*>(&Bw[(size_t)(k0 + r) * Nn + n0 + c]);
            *reinterpret_cast<float4*>(&Bs[r][c]) = v;
        }
        __syncthreads();

#pragma unroll
        for (int kk = 0; kk < 16; kk++) {
            float4 a0 = *reinterpret_cast<const float4*>(&As[kk][ty * 8]);
            float4 a1 = *reinterpret_cast<const float4*>(&As[kk][ty * 8 + 4]);
            float4 b  = *reinterpret_cast<const float4*>(&Bs[kk][tx * 4]);
            float a[8] = {a0.x, a0.y, a0.z, a0.w, a1.x, a1.y, a1.z, a1.w};
            float bb[4] = {b.x, b.y, b.z, b.w};
#pragma unroll
            for (int i = 0; i < 8; i++)
#pragma unroll
                for (int j = 0; j < 4; j++) acc[i][j] += a[i] * bb[j];
        }
        __syncthreads();
    }

    float bv[4];
#pragma unroll
    for (int j = 0; j < 4; j++) bv[j] = bias ? bias[n0 + tx * 4 + j] : 0.f;

#pragma unroll
    for (int i = 0; i < 8; i++) {
        int m = m0 + ty * 8 + i;
        float4 out = make_float4(acc[i][0] + bv[0], acc[i][1] + bv[1],
                                 acc[i][2] + bv[2], acc[i][3] + bv[3]);
        *reinterpret_cast<float4*>(&C[(size_t)m * Nn + n0 + tx * 4]) = out;
    }
}

// ---------------------------------------------------------------------------
// Edge aggregation: H[b*N+row][e*G + g] += XW[e][b*N+col][g]
// grid: (64, B*ECAT), 256 threads; 64 threads (16 float4) per edge, 4 edges concurrent.
// ---------------------------------------------------------------------------
__global__ __launch_bounds__(256)
void aggregate_kernel(const int* __restrict__ A) {
    const int be = blockIdx.y;            // b*4 + e
    const int b = be >> 2, e = be & 3;
    const int* rows = A + ((size_t)be * 2 + 0) * NEDGES;
    const int* cols = A + ((size_t)be * 2 + 1) * NEDGES;
    const int edges_per_block = NEDGES / gridDim.x;   // 256
    const int e0 = blockIdx.x * edges_per_block;
    const int lane = threadIdx.x & 63;    // float4 index within 256-float row
    const int sub  = threadIdx.x >> 6;    // 0..3

    for (int i = e0 + sub; i < e0 + edges_per_block; i += 4) {
        int r = rows[i], c = cols[i];
        float4 v = *reinterpret_cast<const float4*>(
            &d_XW[((size_t)e * Mv + (size_t)b * Nv + c) * Gv + lane * 4]);
        float* dst = &d_H[((size_t)b * Nv + r) * DIN + e * Gv + lane * 4];
        atomicAdd(dst + 0, v.x);
        atomicAdd(dst + 1, v.y);
        atomicAdd(dst + 2, v.z);
        atomicAdd(dst + 3, v.w);
    }
}

// ---------------------------------------------------------------------------
// BatchNorm column reduction: per-column sum and sumsq over M=16384 rows.
// block (32,8), grid (Nn/32, 32). Each block covers 32 columns x 512 rows.
// ---------------------------------------------------------------------------
__global__ void bn_reduce(const float* __restrict__ h, float* __restrict__ sum,
                          float* __restrict__ sumsq, int Nn) {
    const int j = blockIdx.x * 32 + threadIdx.x;
    const int rows_per = Mv / gridDim.y;          // 512
    const int r0 = blockIdx.y * rows_per;
    float s = 0.f, ss = 0.f;
    for (int r = r0 + threadIdx.y; r < r0 + rows_per; r += 8) {
        float v = h[(size_t)r * Nn + j];
        s += v; ss += v * v;
    }
    __shared__ float sm[2][8][32];
    sm[0][threadIdx.y][threadIdx.x] = s;
    sm[1][threadIdx.y][threadIdx.x] = ss;
    __syncthreads();
    if (threadIdx.y == 0) {
#pragma unroll
        for (int t = 1; t < 8; t++) {
            s  += sm[0][t][threadIdx.x];
            ss += sm[1][t][threadIdx.x];
        }
        atomicAdd(&sum[j], s);
        atomicAdd(&sumsq[j], ss);
    }
}

// ---------------------------------------------------------------------------
// BatchNorm apply + ELU (in place)
// ---------------------------------------------------------------------------
__global__ void bn_apply(float* __restrict__ h, const float* __restrict__ sum,
                         const float* __restrict__ sumsq,
                         const float* __restrict__ g, const float* __restrict__ beta,
                         int Nn) {
    size_t idx = (size_t)blockIdx.x * blockDim.x + threadIdx.x;
    size_t total = (size_t)Mv * Nn;
    if (idx >= total) return;
    int j = (int)(idx % Nn);
    const float invM = 1.0f / (float)Mv;
    float mean = sum[j] * invM;
    float var  = sumsq[j] * invM - mean * mean;
    float x = (h[idx] - mean) * rsqrtf(var + BN_EPS) * g[j] + beta[j];
    h[idx] = x > 0.f ? x : expm1f(x);
}

// ---------------------------------------------------------------------------
// launch
// ---------------------------------------------------------------------------
extern "C" void kernel_launch(void* const* d_in, const int* in_sizes, int n_in,
                              void* d_out, int out_size) {
    const int*   A    = (const int*)  d_in[0];
    const float* X    = (const float*)d_in[1];
    const float* Ws   = (const float*)d_in[2];
    const float* W0   = (const float*)d_in[3];
    const float* b0   = (const float*)d_in[4];
    const float* g0   = (const float*)d_in[5];
    const float* be0  = (const float*)d_in[6];
    const float* W1   = (const float*)d_in[7];
    const float* b1   = (const float*)d_in[8];
    const float* g1   = (const float*)d_in[9];
    const float* be1  = (const float*)d_in[10];
    const float* W2   = (const float*)d_in[11];
    const float* b2   = (const float*)d_in[12];
    float* out = (float*)d_out;

    float *pXW, *pH, *ph0, *ph1, *pstats;
    cudaGetSymbolAddress((void**)&pXW, d_XW);
    cudaGetSymbolAddress((void**)&pH, d_H);
    cudaGetSymbolAddress((void**)&ph0, d_h0);
    cudaGetSymbolAddress((void**)&ph1, d_h1);
    cudaGetSymbolAddress((void**)&pstats, d_stats);

    // 1. zero H (accumulator) and BN stat buffers
    zero_kernel<<<2048, 256>>>(pH, ((size_t)Mv * DIN) / 4);
    zero_kernel<<<2, 256>>>(pstats, (4 * 512) / 4);

    // 2. XW[e] = X @ Ws[e]   (M=16384, K=256, Nn=256, batched over e via z)
    {
        dim3 grid(Gv / 64, Mv / 128, ECAT);
        gemm_bias<false, false><<<grid, 256>>>(
            X, Ws, nullptr, pXW, Mv, Gv, Fv,
            /*aStrideZ=*/0, /*bStrideZ=*/(size_t)Fv * Gv, /*cStrideZ=*/(size_t)Mv * Gv);
    }

    // 3. sparse aggregation H[row] += XW[col]
    {
        dim3 grid(64, Bv * ECAT);
        aggregate_kernel<<<grid, 256>>>(A);
    }

    // 4. h0 = relu(H) @ W0^T + b0
    {
        dim3 grid(H1 / 64, Mv / 128, 1);
        gemm_bias<true, true><<<grid, 256>>>(
            pH, W0, b0, ph0, Mv, H1, DIN, 0, 0, 0);
    }

    // 5. BN0 + ELU
    {
        dim3 grid(H1 / 32, 32);
        bn_reduce<<<grid, dim3(32, 8)>>>(ph0, pstats, pstats + 512, H1);
        size_t total = (size_t)Mv * H1;
        bn_apply<<<(unsigned)((total + 255) / 256), 256>>>(ph0, pstats, pstats + 512, g0, be0, H1);
    }

    // 6. h1 = h0 @ W1^T + b1
    {
        dim3 grid(H2 / 64, Mv / 128, 1);
        gemm_bias<true, false><<<grid, 256>>>(
            ph0, W1, b1, ph1, Mv, H2, H1, 0, 0, 0);
    }

    // 7. BN1 + ELU
    {
        dim3 grid(H2 / 32, 32);
        bn_reduce<<<grid, dim3(32, 8)>>>(ph1, pstats + 1024, pstats + 1536, H2);
        size_t total = (size_t)Mv * H2;
        bn_apply<<<(unsigned)((total + 255) / 256), 256>>>(ph1, pstats + 1024, pstats + 1536, g1, be1, H2);
    }

    // 8. out = h1 @ W2^T + b2
    {
        dim3 grid(EMB / 64, Mv / 128, 1);
        gemm_bias<true, false><<<grid, 256>>>(
            ph1, W2, b2, out, Mv, EMB, H2, 0, 0, 0);
    }
}

// round 3
// speedup vs baseline: 1.0159x; 1.0159x over previous
#include <cuda_runtime.h>
#include <cuda_bf16.h>
#include <math.h>

// Problem constants
#define Bv 16
#define Nv 1024
#define Fv 256
#define Gv 256
#define ECAT 4
#define NEDGES 16384
#define EMB 256
#define H1 512
#define H2 512
#define Mv (Bv * Nv)          // 16384 rows
#define DIN (Gv * ECAT)       // 1024
#define BN_EPS 1e-5f

// Scratch (static device globals; allocation-free)
__device__ float d_XW[(size_t)ECAT * Mv * Gv];   // [e][m][g]  64MB
__device__ float d_H [(size_t)Mv * DIN];         // [m][e*G+g] 64MB
__device__ float d_h0[(size_t)Mv * H1];          // 32MB
__device__ float d_h1[(size_t)Mv * H2];          // 32MB
__device__ float d_stats[4 * 512];               // sum0,sumsq0,sum1,sumsq1

// ---------------------------------------------------------------------------
// zero kernel (grid-stride float4)
// ---------------------------------------------------------------------------
__global__ void zero_kernel(float* __restrict__ p, size_t n4) {
    size_t i = (size_t)blockIdx.x * blockDim.x + threadIdx.x;
    size_t stride = (size_t)gridDim.x * blockDim.x;
    float4 z = make_float4(0.f, 0.f, 0.f, 0.f);
    for (; i < n4; i += stride) reinterpret_cast<float4*>(p)[i] = z;
}

// ---------------------------------------------------------------------------
// Generic tiled GEMM:  C[m][n] = sum_k A[m][k] * B(n,k) + bias[n]
//   B_T = true : Bw is [Nn][K] row-major (weight @ W.T case)
//   B_T = false: Bw is [K][Nn] row-major (X @ Ws case)
//   RELU_A: apply relu to A elements as they are loaded
// BM=128, BN=64, BK=16, 256 threads, 8x4 per-thread tile.
// M % 128 == 0, Nn % 64 == 0, K % 16 == 0 guaranteed by problem sizes.
// ---------------------------------------------------------------------------
template<bool B_T, bool RELU_A>
__global__ __launch_bounds__(256)
void gemm_bias(const float* __restrict__ A, const float* __restrict__ Bw,
               const float* __restrict__ bias, float* __restrict__ C,
               int M, int Nn, int K,
               size_t aStrideZ, size_t bStrideZ, size_t cStrideZ) {
    A  += (size_t)blockIdx.z * aStrideZ;
    Bw += (size_t)blockIdx.z * bStrideZ;
    C  += (size_t)blockIdx.z * cStrideZ;

    __shared__ float As[16][128];
    __shared__ float Bs[16][64];

    const int m0 = blockIdx.y * 128;
    const int n0 = blockIdx.x * 64;
    const int tid = threadIdx.x;
    const int tx = tid & 15;          // 16 threads across n (4 cols each)
    const int ty = tid >> 4;          // 16 threads across m (8 rows each)

    float acc[8][4];
#pragma unroll
    for (int i = 0; i < 8; i++)
#pragma unroll
        for (int j = 0; j < 4; j++) acc[i][j] = 0.f;

    for (int k0 = 0; k0 < K; k0 += 16) {
        // --- load A tile: 128x16 = 512 float4, 2 per thread ---
#pragma unroll
        for (int it = 0; it < 2; it++) {
            int idx = tid + it * 256;       // float4 slot
            int r = idx >> 2;               // row (4 float4 per row)
            int c = (idx & 3) << 2;         // k-col
            float4 v = *reinterpret_cast<const float4*>(&A[(size_t)(m0 + r) * K + k0 + c]);
            if (RELU_A) {
                v.x = fmaxf(v.x, 0.f); v.y = fmaxf(v.y, 0.f);
                v.z = fmaxf(v.z, 0.f); v.w = fmaxf(v.w, 0.f);
            }
            As[c + 0][r] = v.x; As[c + 1][r] = v.y;
            As[c + 2][r] = v.z; As[c + 3][r] = v.w;
        }
        // --- load B tile: 64x16 (B_T) or 16x64 (NT) = 256 float4, 1 per thread ---
        if (B_T) {
            int r = tid >> 2;               // n-row within tile (0..63)
            int c = (tid & 3) << 2;         // k-col
            float4 v = *reinterpret_cast<const float4*>(&Bw[(size_t)(n0 + r) * K + k0 + c]);
            Bs[c + 0][r] = v.x; Bs[c + 1][r] = v.y;
            Bs[c + 2][r] = v.z; Bs[c + 3][r] = v.w;
        } else {
            int r = tid >> 4;               // k-row (0..15)
            int c = (tid & 15) << 2;        // n-col
            float4 v = *reinterpret_cast<const float4*>(&Bw[(size_t)(k0 + r) * Nn + n0 + c]);
            *reinterpret_cast<float4*>(&Bs[r][c]) = v;
        }
        __syncthreads();

#pragma unroll
        for (int kk = 0; kk < 16; kk++) {
            float4 a0 = *reinterpret_cast<const float4*>(&As[kk][ty * 8]);
            float4 a1 = *reinterpret_cast<const float4*>(&As[kk][ty * 8 + 4]);
            float4 b  = *reinterpret_cast<const float4*>(&Bs[kk][tx * 4]);
            float a[8] = {a0.x, a0.y, a0.z, a0.w, a1.x, a1.y, a1.z, a1.w};
            float bb[4] = {b.x, b.y, b.z, b.w};
#pragma unroll
            for (int i = 0; i < 8; i++)
#pragma unroll
                for (int j = 0; j < 4; j++) acc[i][j] += a[i] * bb[j];
        }
        __syncthreads();
    }

    float bv[4];
#pragma unroll
    for (int j = 0; j < 4; j++) bv[j] = bias ? bias[n0 + tx * 4 + j] : 0.f;

#pragma unroll
    for (int i = 0; i < 8; i++) {
        int m = m0 + ty * 8 + i;
        float4 out = make_float4(acc[i][0] + bv[0], acc[i][1] + bv[1],
                                 acc[i][2] + bv[2], acc[i][3] + bv[3]);
        *reinterpret_cast<float4*>(&C[(size_t)m * Nn + n0 + tx * 4]) = out;
    }
}

// ---------------------------------------------------------------------------
// Edge aggregation: H[b*N+row][e*G + g] += XW[e][b*N+col][g]
// grid: (64, B*ECAT), 256 threads; 64 threads (16 float4) per edge, 4 edges concurrent.
// ---------------------------------------------------------------------------
__global__ __launch_bounds__(256)
void aggregate_kernel(const int* __restrict__ A) {
    const int be = blockIdx.y;            // b*4 + e
    const int b = be >> 2, e = be & 3;
    const int* rows = A + ((size_t)be * 2 + 0) * NEDGES;
    const int* cols = A + ((size_t)be * 2 + 1) * NEDGES;
    const int edges_per_block = NEDGES / gridDim.x;   // 256
    const int e0 = blockIdx.x * edges_per_block;
    const int lane = threadIdx.x & 63;    // float4 index within 256-float row
    const int sub  = threadIdx.x >> 6;    // 0..3

    for (int i = e0 + sub; i < e0 + edges_per_block; i += 4) {
        int r = rows[i], c = cols[i];
        float4 v = *reinterpret_cast<const float4*>(
            &d_XW[((size_t)e * Mv + (size_t)b * Nv + c) * Gv + lane * 4]);
        float* dst = &d_H[((size_t)b * Nv + r) * DIN + e * Gv + lane * 4];
        atomicAdd(dst + 0, v.x);
        atomicAdd(dst + 1, v.y);
        atomicAdd(dst + 2, v.z);
        atomicAdd(dst + 3, v.w);
    }
}

// ---------------------------------------------------------------------------
// BatchNorm column reduction: per-column sum and sumsq over M=16384 rows.
// block (32,8), grid (Nn/32, 32). Each block covers 32 columns x 512 rows.
// ---------------------------------------------------------------------------
__global__ void bn_reduce(const float* __restrict__ h, float* __restrict__ sum,
                          float* __restrict__ sumsq, int Nn) {
    const int j = blockIdx.x * 32 + threadIdx.x;
    const int rows_per = Mv / gridDim.y;          // 512
    const int r0 = blockIdx.y * rows_per;
    float s = 0.f, ss = 0.f;
    for (int r = r0 + threadIdx.y; r < r0 + rows_per; r += 8) {
        float v = h[(size_t)r * Nn + j];
        s += v; ss += v * v;
    }
    __shared__ float sm[2][8][32];
    sm[0][threadIdx.y][threadIdx.x] = s;
    sm[1][threadIdx.y][threadIdx.x] = ss;
    __syncthreads();
    if (threadIdx.y == 0) {
#pragma unroll
        for (int t = 1; t < 8; t++) {
            s  += sm[0][t][threadIdx.x];
            ss += sm[1][t][threadIdx.x];
        }
        atomicAdd(&sum[j], s);
        atomicAdd(&sumsq[j], ss);
    }
}

// ---------------------------------------------------------------------------
// BatchNorm apply + ELU (in place)
// ---------------------------------------------------------------------------
__global__ void bn_apply(float* __restrict__ h, const float* __restrict__ sum,
                         const float* __restrict__ sumsq,
                         const float* __restrict__ g, const float* __restrict__ beta,
                         int Nn) {
    size_t idx = (size_t)blockIdx.x * blockDim.x + threadIdx.x;
    size_t total = (size_t)Mv * Nn;
    if (idx >= total) return;
    int j = (int)(idx % Nn);
    const float invM = 1.0f / (float)Mv;
    float mean = sum[j] * invM;
    float var  = sumsq[j] * invM - mean * mean;
    float x = (h[idx] - mean) * rsqrtf(var + BN_EPS) * g[j] + beta[j];
    h[idx] = x > 0.f ? x : expm1f(x);
}

// ---------------------------------------------------------------------------
// launch
// ---------------------------------------------------------------------------
extern "C" void kernel_launch(void* const* d_in, const int* in_sizes, int n_in,
                              void* d_out, int out_size) {
    const int*   A    = (const int*)  d_in[0];
    const float* X    = (const float*)d_in[1];
    const float* Ws   = (const float*)d_in[2];
    const float* W0   = (const float*)d_in[3];
    const float* b0   = (const float*)d_in[4];
    const float* g0   = (const float*)d_in[5];
    const float* be0  = (const float*)d_in[6];
    const float* W1   = (const float*)d_in[7];
    const float* b1   = (const float*)d_in[8];
    const float* g1   = (const float*)d_in[9];
    const float* be1  = (const float*)d_in[10];
    const float* W2   = (const float*)d_in[11];
    const float* b2   = (const float*)d_in[12];
    float* out = (float*)d_out;

    float *pXW, *pH, *ph0, *ph1, *pstats;
    cudaGetSymbolAddress((void**)&pXW, d_XW);
    cudaGetSymbolAddress((void**)&pH, d_H);
    cudaGetSymbolAddress((void**)&ph0, d_h0);
    cudaGetSymbolAddress((void**)&ph1, d_h1);
    cudaGetSymbolAddress((void**)&pstats, d_stats);

    // 1. zero H (accumulator) and BN stat buffers
    zero_kernel<<<2048, 256>>>(pH, ((size_t)Mv * DIN) / 4);
    zero_kernel<<<2, 256>>>(pstats, (4 * 512) / 4);

    // 2. XW[e] = X @ Ws[e]   (M=16384, K=256, Nn=256, batched over e via z)
    {
        dim3 grid(Gv / 64, Mv / 128, ECAT);
        gemm_bias<false, false><<<grid, 256>>>(
            X, Ws, nullptr, pXW, Mv, Gv, Fv,
            /*aStrideZ=*/0, /*bStrideZ=*/(size_t)Fv * Gv, /*cStrideZ=*/(size_t)Mv * Gv);
    }

    // 3. sparse aggregation H[row] += XW[col]
    {
        dim3 grid(64, Bv * ECAT);
        aggregate_kernel<<<grid, 256>>>(A);
    }

    // 4. h0 = relu(H) @ W0^T + b0
    {
        dim3 grid(H1 / 64, Mv / 128, 1);
        gemm_bias<true, true><<<grid, 256>>>(
            pH, W0, b0, ph0, Mv, H1, DIN, 0, 0, 0);
    }

    // 5. BN0 + ELU
    {
        dim3 grid(H1 / 32, 32);
        bn_reduce<<<grid, dim3(32, 8)>>>(ph0, pstats, pstats + 512, H1);
        size_t total = (size_t)Mv * H1;
        bn_apply<<<(unsigned)((total + 255) / 256), 256>>>(ph0, pstats, pstats + 512, g0, be0, H1);
    }

    // 6. h1 = h0 @ W1^T + b1
    {
        dim3 grid(H2 / 64, Mv / 128, 1);
        gemm_bias<true, false><<<grid, 256>>>(
            ph0, W1, b1, ph1, Mv, H2, H1, 0, 0, 0);
    }

    // 7. BN1 + ELU
    {
        dim3 grid(H2 / 32, 32);
        bn_reduce<<<grid, dim3(32, 8)>>>(ph1, pstats + 1024, pstats + 1536, H2);
        size_t total = (size_t)Mv * H2;
        bn_apply<<<(unsigned)((total + 255) / 256), 256>>>(ph1, pstats + 1024, pstats + 1536, g1, be1, H2);
    }

    // 8. out = h1 @ W2^T + b2
    {
        dim3 grid(EMB / 64, Mv / 128, 1);
        gemm_bias<true, false><<<grid, 256>>>(
            ph1, W2, b2, out, Mv, EMB, H2, 0, 0, 0);
    }
}